// round 1
// baseline (speedup 1.0000x reference)
#include <cuda_runtime.h>

#define N_TOK 8192
#define DDIM  256
#define HDIM  64
#define NEXP  32
#define TM    32      // tokens per ffn tile
#define TILES 32      // max tiles per expert (supports 1024 tokens/expert; mean is 256)

// ---------------- scratch (no allocations allowed) ----------------
__device__ int g_idx[N_TOK];
__device__ int g_counts[NEXP];
__device__ int g_off[NEXP + 1];
__device__ int g_cursor[NEXP];
__device__ int g_perm[N_TOK];

// ---------------- kernel 1: zero histograms ----------------
__global__ void k_init() {
    int t = threadIdx.x;
    if (t < NEXP) { g_counts[t] = 0; g_cursor[t] = 0; }
}

// ---------------- kernel 2: router + argmax ----------------
// 1 warp per token. Lane l owns d in {4l..4l+3} U {128+4l..131+4l} (all loads coalesced).
// Each lane accumulates partials for all 32 experts, then a full xor-butterfly
// reduction gives every lane the complete logits; lane 0 does the argmax.
__global__ void __launch_bounds__(256) k_router(const float* __restrict__ x,
                                                const float* __restrict__ rw,
                                                const float* __restrict__ rb) {
    int warp = threadIdx.x >> 5;
    int lane = threadIdx.x & 31;
    int n = blockIdx.x * 8 + warp;

    const float4* X4 = (const float4*)x;
    const float4* W4 = (const float4*)rw;

    float4 x0 = X4[n * 64 + lane];
    float4 x1 = X4[n * 64 + 32 + lane];

    float p[NEXP];
#pragma unroll
    for (int e = 0; e < NEXP; e++) {
        float4 w0 = W4[e * 64 + lane];
        float4 w1 = W4[e * 64 + 32 + lane];
        p[e] = x0.x * w0.x + x0.y * w0.y + x0.z * w0.z + x0.w * w0.w
             + x1.x * w1.x + x1.y * w1.y + x1.z * w1.z + x1.w * w1.w;
    }

#pragma unroll
    for (int m = 1; m < 32; m <<= 1) {
#pragma unroll
        for (int e = 0; e < NEXP; e++)
            p[e] += __shfl_xor_sync(0xffffffffu, p[e], m);
    }

    if (lane == 0) {
        float best = p[0] + rb[0];
        int bi = 0;
#pragma unroll
        for (int e = 1; e < NEXP; e++) {
            float v = p[e] + rb[e];
            if (v > best) { best = v; bi = e; }   // strict > == first-max (jnp.argmax)
        }
        g_idx[n] = bi;
        atomicAdd(&g_counts[bi], 1);
    }
}

// ---------------- kernel 3: exclusive scan over 32 experts ----------------
__global__ void k_scan() {
    if (threadIdx.x == 0) {
        int s = 0;
        for (int e = 0; e < NEXP; e++) {
            g_off[e] = s;
            g_cursor[e] = s;
            s += g_counts[e];
        }
        g_off[NEXP] = s;
    }
}

// ---------------- kernel 4: scatter tokens into per-expert groups ----------------
__global__ void k_scatter() {
    int n = blockIdx.x * blockDim.x + threadIdx.x;
    if (n < N_TOK) {
        int e = g_idx[n];
        int pos = atomicAdd(&g_cursor[e], 1);
        g_perm[pos] = n;
    }
}

// ---------------- kernel 5: grouped expert FFN ----------------
// grid = (TILES, NEXP), 64 threads. Tile = up to 32 tokens of one expert.
// GEMM1: H[32x64] = X[32x256] @ W1[e]   (K-chunked, X transposed in smem)
// GEMM2: O[32x256] = relu(H) @ W2[e]    (4 chunks of 64 cols, W buffer reused)
__global__ void __launch_bounds__(64) k_ffn(const float* __restrict__ x,
                                            const float* __restrict__ W1,
                                            const float* __restrict__ b1,
                                            const float* __restrict__ W2,
                                            const float* __restrict__ b2,
                                            float* __restrict__ out) {
    const int e    = blockIdx.y;
    const int tile = blockIdx.x;

    const int off0 = g_off[e];
    const int cnt  = g_off[e + 1] - off0;
    if (tile * TM >= cnt) return;
    const int nt   = min(TM, cnt - tile * TM);
    const int base = off0 + tile * TM;

    const int tid = threadIdx.x;
    const int tx  = tid & 7;    // 8 col-groups
    const int ty  = tid >> 3;   // 8 row-groups (4 tokens each)

    __shared__ int   toks[TM];
    __shared__ float Xs[32][36];      // [k][token], padded
    __shared__ float Hs[HDIM][36];    // [h][token], padded
    __shared__ float Wbuf[64 * 64];   // GEMM1: [32][64] used; GEMM2: [64][64]

    if (tid < TM) toks[tid] = g_perm[base + min(tid, nt - 1)];
    __syncthreads();

    const float4* Xg = (const float4*)x;

    float acc[4][8];
#pragma unroll
    for (int i = 0; i < 4; i++)
#pragma unroll
        for (int j = 0; j < 8; j++) acc[i][j] = 0.f;

    // ================= GEMM1: K = 256 in chunks of 32 =================
    for (int k0 = 0; k0 < DDIM; k0 += 32) {
        // stage X chunk, transposed: Xs[k][tok]
#pragma unroll
        for (int i = 0; i < 4; i++) {
            int lin = tid + i * 64;          // 0..255
            int tok = lin & 31;
            int kq  = lin >> 5;              // 0..7 (float4 within chunk)
            float4 v = Xg[(size_t)toks[tok] * 64 + (k0 >> 2) + kq];
            Xs[kq * 4 + 0][tok] = v.x;
            Xs[kq * 4 + 1][tok] = v.y;
            Xs[kq * 4 + 2][tok] = v.z;
            Xs[kq * 4 + 3][tok] = v.w;
        }
        // stage W1 chunk: rows k0..k0+31, all 64 h
        const float4* Wg = (const float4*)(W1 + (size_t)e * DDIM * HDIM + (size_t)k0 * HDIM);
#pragma unroll
        for (int i = 0; i < 8; i++) {
            int lin = tid + i * 64;          // 0..511
            int k   = lin >> 4;
            int h4  = lin & 15;
            *(float4*)&Wbuf[k * 64 + h4 * 4] = Wg[lin];
        }
        __syncthreads();

#pragma unroll
        for (int k = 0; k < 32; k++) {
            float4 a  = *(const float4*)&Xs[k][ty * 4];
            float4 b0 = *(const float4*)&Wbuf[k * 64 + tx * 4];
            float4 b1v = *(const float4*)&Wbuf[k * 64 + 32 + tx * 4];
            float av[4] = {a.x, a.y, a.z, a.w};
            float bv[8] = {b0.x, b0.y, b0.z, b0.w, b1v.x, b1v.y, b1v.z, b1v.w};
#pragma unroll
            for (int i = 0; i < 4; i++)
#pragma unroll
                for (int j = 0; j < 8; j++) acc[i][j] += av[i] * bv[j];
        }
        __syncthreads();
    }

    // bias + relu -> Hs[h][tok] (transposed for GEMM2 a-loads)
    {
        float4 bb0 = *(const float4*)&b1[e * HDIM + tx * 4];
        float4 bb1 = *(const float4*)&b1[e * HDIM + 32 + tx * 4];
        float bb[8] = {bb0.x, bb0.y, bb0.z, bb0.w, bb1.x, bb1.y, bb1.z, bb1.w};
#pragma unroll
        for (int i = 0; i < 4; i++) {
            int tok = ty * 4 + i;
#pragma unroll
            for (int j = 0; j < 8; j++) {
                float v = acc[i][j] + bb[j];
                int h = (j < 4) ? (tx * 4 + j) : (32 + tx * 4 + (j - 4));
                Hs[h][tok] = v > 0.f ? v : 0.f;
            }
        }
    }

    // ================= GEMM2: 4 chunks of 64 output cols =================
    const float4* W2g = (const float4*)(W2 + (size_t)e * HDIM * DDIM);
    for (int c = 0; c < 4; c++) {
        __syncthreads();   // Hs ready (first iter) / Wbuf reads done (later iters)
#pragma unroll
        for (int i = 0; i < 16; i++) {
            int lin = tid + i * 64;          // 0..1023
            int k   = lin >> 4;
            int n4  = lin & 15;
            *(float4*)&Wbuf[k * 64 + n4 * 4] = W2g[k * 64 + c * 16 + n4];
        }
        __syncthreads();

#pragma unroll
        for (int i = 0; i < 4; i++)
#pragma unroll
            for (int j = 0; j < 8; j++) acc[i][j] = 0.f;

#pragma unroll 8
        for (int k = 0; k < HDIM; k++) {
            float4 a   = *(const float4*)&Hs[k][ty * 4];
            float4 b0  = *(const float4*)&Wbuf[k * 64 + tx * 4];
            float4 b1v = *(const float4*)&Wbuf[k * 64 + 32 + tx * 4];
            float av[4] = {a.x, a.y, a.z, a.w};
            float bv[8] = {b0.x, b0.y, b0.z, b0.w, b1v.x, b1v.y, b1v.z, b1v.w};
#pragma unroll
            for (int i = 0; i < 4; i++)
#pragma unroll
                for (int j = 0; j < 8; j++) acc[i][j] += av[i] * bv[j];
        }

        // epilogue: bias + relu + store
        float4 c0 = *(const float4*)&b2[e * DDIM + c * 64 + tx * 4];
        float4 c1 = *(const float4*)&b2[e * DDIM + c * 64 + 32 + tx * 4];
#pragma unroll
        for (int i = 0; i < 4; i++) {
            int ti = ty * 4 + i;
            if (ti < nt) {
                size_t row = (size_t)toks[ti] * DDIM;
                float4 r0, r1;
                r0.x = fmaxf(acc[i][0] + c0.x, 0.f);
                r0.y = fmaxf(acc[i][1] + c0.y, 0.f);
                r0.z = fmaxf(acc[i][2] + c0.z, 0.f);
                r0.w = fmaxf(acc[i][3] + c0.w, 0.f);
                r1.x = fmaxf(acc[i][4] + c1.x, 0.f);
                r1.y = fmaxf(acc[i][5] + c1.y, 0.f);
                r1.z = fmaxf(acc[i][6] + c1.z, 0.f);
                r1.w = fmaxf(acc[i][7] + c1.w, 0.f);
                *(float4*)&out[row + c * 64 + tx * 4] = r0;
                *(float4*)&out[row + c * 64 + 32 + tx * 4] = r1;
            }
        }
    }
}

// ---------------- launch ----------------
extern "C" void kernel_launch(void* const* d_in, const int* in_sizes, int n_in,
                              void* d_out, int out_size) {
    const float* x   = (const float*)d_in[0];
    const float* rw  = (const float*)d_in[1];
    const float* rb  = (const float*)d_in[2];
    const float* W1  = (const float*)d_in[3];
    const float* b1  = (const float*)d_in[4];
    const float* W2  = (const float*)d_in[5];
    const float* b2  = (const float*)d_in[6];
    float* out = (float*)d_out;

    k_init<<<1, 64>>>();
    k_router<<<N_TOK / 8, 256>>>(x, rw, rb);
    k_scan<<<1, 32>>>();
    k_scatter<<<N_TOK / 256, 256>>>();
    dim3 grid(TILES, NEXP);
    k_ffn<<<grid, 64>>>(x, W1, b1, W2, b2, out);
}